// round 2
// baseline (speedup 1.0000x reference)
#include <cuda_runtime.h>
#include <math.h>
#include <stdint.h>

#define EMBED 3072
#define NQ 32
#define NKV 8
#define HD 96
#define BATCH 2
#define SEQ 2048
#define ROWS (BATCH*SEQ)                 // 4096
#define QKV_N (NQ*HD + 2*NKV*HD)         // 4608
#define KOFF (NQ*HD)                     // 3072
#define VOFF (NQ*HD + NKV*HD)            // 3840
#define GROUPS (NQ/NKV)                  // 4

// Scratch (allocation-free rule: __device__ globals)
__device__ float g_qkv[ROWS * QKV_N];    // ~75.5 MB
__device__ float g_attn[ROWS * EMBED];   // ~50.3 MB

// ---------------------------------------------------------------------------
// GEMM: C[M,N] = A[M,K] * B[N,K]^T   (both row-major, K contiguous)
// 128x128 tile, BK=8, 256 threads, 8x8 register micro-tile per thread.
// M,N,K must be multiples of 128/128/8 (true for all calls here).
// ---------------------------------------------------------------------------
__global__ __launch_bounds__(256) void gemm_nt(const float* __restrict__ A,
                                               const float* __restrict__ Bm,
                                               float* __restrict__ C,
                                               int M, int N, int K)
{
    __shared__ float As[8][128];
    __shared__ float Bs[8][128];

    const int tid = threadIdx.x;
    const int m0 = blockIdx.y * 128;
    const int n0 = blockIdx.x * 128;

    const int lr = tid >> 1;           // 0..127 (row within tile)
    const int lk = (tid & 1) * 4;      // 0 or 4

    const float* Aptr = A + (size_t)(m0 + lr) * K + lk;
    const float* Bptr = Bm + (size_t)(n0 + lr) * K + lk;

    const int ty = tid >> 4;           // 0..15
    const int tx = tid & 15;           // 0..15

    float acc[8][8];
#pragma unroll
    for (int i = 0; i < 8; i++)
#pragma unroll
        for (int j = 0; j < 8; j++) acc[i][j] = 0.0f;

    for (int k0 = 0; k0 < K; k0 += 8) {
        float4 av = *(const float4*)(Aptr + k0);
        float4 bv = *(const float4*)(Bptr + k0);
        As[lk + 0][lr] = av.x; As[lk + 1][lr] = av.y;
        As[lk + 2][lr] = av.z; As[lk + 3][lr] = av.w;
        Bs[lk + 0][lr] = bv.x; Bs[lk + 1][lr] = bv.y;
        Bs[lk + 2][lr] = bv.z; Bs[lk + 3][lr] = bv.w;
        __syncthreads();

#pragma unroll
        for (int k = 0; k < 8; k++) {
            float4 a0 = *(const float4*)&As[k][ty * 8];
            float4 a1 = *(const float4*)&As[k][ty * 8 + 4];
            float4 b0 = *(const float4*)&Bs[k][tx * 8];
            float4 b1 = *(const float4*)&Bs[k][tx * 8 + 4];
            float af[8] = {a0.x, a0.y, a0.z, a0.w, a1.x, a1.y, a1.z, a1.w};
            float bf[8] = {b0.x, b0.y, b0.z, b0.w, b1.x, b1.y, b1.z, b1.w};
#pragma unroll
            for (int i = 0; i < 8; i++)
#pragma unroll
                for (int j = 0; j < 8; j++)
                    acc[i][j] = fmaf(af[i], bf[j], acc[i][j]);
        }
        __syncthreads();
    }

#pragma unroll
    for (int i = 0; i < 8; i++) {
        float* crow = C + (size_t)(m0 + ty * 8 + i) * N + n0 + tx * 8;
        float4 o0 = {acc[i][0], acc[i][1], acc[i][2], acc[i][3]};
        float4 o1 = {acc[i][4], acc[i][5], acc[i][6], acc[i][7]};
        *(float4*)(crow)     = o0;
        *(float4*)(crow + 4) = o1;
    }
}

// ---------------------------------------------------------------------------
// RoPE applied in-place to Q (heads 0..31) and K (heads 32..39) of g_qkv.
// Q and K regions are contiguous: head h in [0,40) lives at offset h*HD.
// ---------------------------------------------------------------------------
__global__ void rope_kernel(float* __restrict__ qkv,
                            const int* __restrict__ positions)
{
    const int total = ROWS * (NQ + NKV) * (HD / 2);
    int idx = blockIdx.x * blockDim.x + threadIdx.x;
    if (idx >= total) return;

    const int i   = idx % (HD / 2);                 // 0..47
    const int h   = (idx / (HD / 2)) % (NQ + NKV);  // 0..39
    const int row = idx / ((HD / 2) * (NQ + NKV));  // 0..4095

    const int pos = positions[row & (SEQ - 1)];
    const float e = (float)(2 * i) / (float)HD;
    // 10000^(-e) = exp(-e * ln(10000))
    const float inv_freq = expf(-e * 9.210340371976184f);
    const float ang = (float)pos * inv_freq;
    float s, c;
    sincosf(ang, &s, &c);

    float* base = qkv + (size_t)row * QKV_N + h * HD + i;
    const float t1 = base[0];
    const float t2 = base[HD / 2];
    base[0]      = t1 * c - t2 * s;
    base[HD / 2] = t2 * c + t1 * s;
}

// ---------------------------------------------------------------------------
// Causal GQA flash attention, fp32.
// Block: (qb, qh, b). 64 query rows x 64-key tiles, online softmax.
// 256 threads = 16x16; S micro-tile 4x4, O micro-tile 4 rows x 6 cols.
// ---------------------------------------------------------------------------
#define ATTN_SMEM_FLOATS (96*64 + 96*64 + 64*96 + 64*65 + 3*64)
#define ATTN_SMEM_BYTES  (ATTN_SMEM_FLOATS * 4)

__global__ __launch_bounds__(256) void attn_kernel(const float* __restrict__ qkv,
                                                   float* __restrict__ out)
{
    extern __shared__ float sm[];
    float* Qs = sm;                 // [96][64]  k-major
    float* Ks = Qs + 96 * 64;       // [96][64]  k-major
    float* Vs = Ks + 96 * 64;       // [64][96]  row-major (key, hd)
    float* Ss = Vs + 64 * 96;       // [64][65]  padded
    float* Ms = Ss + 64 * 65;       // row running max
    float* Ls = Ms + 64;            // row running sum
    float* Cs = Ls + 64;            // row correction factor

    const int qb  = blockIdx.x;     // 0..31
    const int qh  = blockIdx.y;     // 0..31
    const int bb  = blockIdx.z;     // 0..1
    const int kvh = qh >> 2;        // GROUPS = 4
    const int tid = threadIdx.x;
    const int ty = tid >> 4, tx = tid & 15;
    const int r0 = ty * 4;          // my 4 rows
    const int c0 = tx * 6;          // my 6 output cols
    const float scale = 0.10206207261596577f;  // 96^-0.5

    // Load Q tile (transposed to k-major)
    for (int idx = tid; idx < 64 * 96; idx += 256) {
        const int r = idx / 96, d = idx % 96;
        Qs[d * 64 + r] = qkv[(size_t)(bb * SEQ + qb * 64 + r) * QKV_N + qh * HD + d];
    }
    if (tid < 64) { Ms[tid] = -INFINITY; Ls[tid] = 0.0f; }

    float o[4][6];
#pragma unroll
    for (int i = 0; i < 4; i++)
#pragma unroll
        for (int c = 0; c < 6; c++) o[i][c] = 0.0f;

    for (int kb = 0; kb <= qb; kb++) {
        __syncthreads();  // protect Ks/Vs/Ss reuse vs previous PV phase

        // Load K (transposed) and V (row-major)
        for (int idx = tid; idx < 64 * 96; idx += 256) {
            const int r = idx / 96, d = idx % 96;
            const float* p = qkv + (size_t)(bb * SEQ + kb * 64 + r) * QKV_N + kvh * HD + d;
            Ks[d * 64 + r] = p[KOFF];
            Vs[r * 96 + d] = p[VOFF];
        }
        __syncthreads();

        // S = Q K^T (64x64x96)
        float sa[4][4];
#pragma unroll
        for (int i = 0; i < 4; i++)
#pragma unroll
            for (int j = 0; j < 4; j++) sa[i][j] = 0.0f;

#pragma unroll 8
        for (int k = 0; k < 96; k++) {
            float4 qa = *(const float4*)&Qs[k * 64 + r0];
            float4 ka = *(const float4*)&Ks[k * 64 + tx * 4];
            float qf[4] = {qa.x, qa.y, qa.z, qa.w};
            float kf[4] = {ka.x, ka.y, ka.z, ka.w};
#pragma unroll
            for (int i = 0; i < 4; i++)
#pragma unroll
                for (int j = 0; j < 4; j++)
                    sa[i][j] = fmaf(qf[i], kf[j], sa[i][j]);
        }

        // scale + causal mask + stash
#pragma unroll
        for (int i = 0; i < 4; i++) {
            const int qrow = qb * 64 + r0 + i;
#pragma unroll
            for (int j = 0; j < 4; j++) {
                const int kc = kb * 64 + tx * 4 + j;
                float v = sa[i][j] * scale;
                if (kc > qrow) v = -1e30f;
                Ss[(r0 + i) * 65 + tx * 4 + j] = v;
            }
        }
        __syncthreads();

        // Online softmax: one thread per row
        if (tid < 64) {
            const float mo = Ms[tid];
            float rm = mo;
            for (int j = 0; j < 64; j++) rm = fmaxf(rm, Ss[tid * 65 + j]);
            const float co = __expf(mo - rm);   // exp(-inf)=0 on first tile
            float l = Ls[tid] * co;
            for (int j = 0; j < 64; j++) {
                const float p = __expf(Ss[tid * 65 + j] - rm);
                Ss[tid * 65 + j] = p;
                l += p;
            }
            Ms[tid] = rm; Ls[tid] = l; Cs[tid] = co;
        }
        __syncthreads();

        // Rescale O, then O += P @ V
        float cf[4];
#pragma unroll
        for (int i = 0; i < 4; i++) {
            cf[i] = Cs[r0 + i];
#pragma unroll
            for (int c = 0; c < 6; c++) o[i][c] *= cf[i];
        }
#pragma unroll 4
        for (int j = 0; j < 64; j++) {
            float p0 = Ss[(r0 + 0) * 65 + j];
            float p1 = Ss[(r0 + 1) * 65 + j];
            float p2 = Ss[(r0 + 2) * 65 + j];
            float p3 = Ss[(r0 + 3) * 65 + j];
            float2 v0 = *(const float2*)&Vs[j * 96 + c0];
            float2 v1 = *(const float2*)&Vs[j * 96 + c0 + 2];
            float2 v2 = *(const float2*)&Vs[j * 96 + c0 + 4];
            float vf[6] = {v0.x, v0.y, v1.x, v1.y, v2.x, v2.y};
            float pf[4] = {p0, p1, p2, p3};
#pragma unroll
            for (int i = 0; i < 4; i++)
#pragma unroll
                for (int c = 0; c < 6; c++)
                    o[i][c] = fmaf(pf[i], vf[c], o[i][c]);
        }
    }

    // Finalize: divide by l, write to attn output buffer (b, s, NQ*HD)
#pragma unroll
    for (int i = 0; i < 4; i++) {
        const float inv_l = 1.0f / Ls[r0 + i];
        float* orow = out + (size_t)(bb * SEQ + qb * 64 + r0 + i) * EMBED + qh * HD + c0;
#pragma unroll
        for (int c = 0; c < 6; c++) orow[c] = o[i][c] * inv_l;
    }
}

// ---------------------------------------------------------------------------
// Launch
// ---------------------------------------------------------------------------
extern "C" void kernel_launch(void* const* d_in, const int* in_sizes, int n_in,
                              void* d_out, int out_size)
{
    const float* x         = (const float*)d_in[0];   // (2,2048,3072)
    const int*   positions = (const int*)d_in[1];     // (2048,)
    // d_in[2] = mask (causal, hardcoded)
    const float* W_qkv     = (const float*)d_in[3];   // (4608,3072)
    const float* W_o       = (const float*)d_in[4];   // (3072,3072)
    float* out = (float*)d_out;

    float* qkv;  cudaGetSymbolAddress((void**)&qkv,  g_qkv);
    float* attn; cudaGetSymbolAddress((void**)&attn, g_attn);

    cudaFuncSetAttribute(attn_kernel,
                         cudaFuncAttributeMaxDynamicSharedMemorySize,
                         ATTN_SMEM_BYTES);

    // 1) QKV projection: [4096,4608] = x[4096,3072] @ W_qkv^T
    gemm_nt<<<dim3(QKV_N / 128, ROWS / 128), 256>>>(x, W_qkv, qkv,
                                                    ROWS, QKV_N, EMBED);

    // 2) RoPE on Q and K in place
    {
        const int total = ROWS * (NQ + NKV) * (HD / 2);
        rope_kernel<<<(total + 255) / 256, 256>>>(qkv, positions);
    }

    // 3) Causal GQA attention -> attn[4096,3072]
    attn_kernel<<<dim3(SEQ / 64, NQ, BATCH), 256, ATTN_SMEM_BYTES>>>(qkv, attn);

    // 4) Output projection: out = attn @ W_o^T
    gemm_nt<<<dim3(EMBED / 128, ROWS / 128), 256>>>(attn, W_o, out,
                                                    ROWS, EMBED, EMBED);
}

// round 5
// speedup vs baseline: 1.3555x; 1.3555x over previous
#include <cuda_runtime.h>
#include <math.h>
#include <stdint.h>

#define EMBED 3072
#define NQ 32
#define NKV 8
#define HD 96
#define BATCH 2
#define SEQ 2048
#define ROWS (BATCH*SEQ)                 // 4096
#define QKV_N (NQ*HD + 2*NKV*HD)         // 4608
#define KOFF (NQ*HD)                     // 3072
#define VOFF (NQ*HD + NKV*HD)            // 3840
#define GROUPS (NQ/NKV)                  // 4

// Scratch (allocation-free rule: __device__ globals)
__device__ float g_qkv[ROWS * QKV_N];    // ~75.5 MB
__device__ float g_attn[ROWS * EMBED];   // ~50.3 MB

// ---------------------------------------------------------------------------
// TF32 tensor-core GEMM with split-precision (3xTF32) error compensation.
// C[M,N] = A[M,K] * B[N,K]^T  (both row-major, K contiguous).
// CTA tile 128x128, BK=32, 8 warps (4x2), warp tile 32x64.
// mma.sync.aligned.m16n8k8.row.col.f32.tf32.tf32.f32
// ---------------------------------------------------------------------------
#define BM 128
#define BN 128
#define BK 32
#define LDS_STRIDE 36   // BK + 4 pad -> conflict-free fragment loads

__device__ __forceinline__ uint32_t f2tf32(float x) {
    uint32_t r;
    asm("cvt.rna.tf32.f32 %0, %1;" : "=r"(r) : "f"(x));
    return r;
}

__device__ __forceinline__ void mma_tf32(float* d, const uint32_t* a, const uint32_t* b) {
    asm volatile(
        "mma.sync.aligned.m16n8k8.row.col.f32.tf32.tf32.f32 "
        "{%0,%1,%2,%3}, {%4,%5,%6,%7}, {%8,%9}, {%0,%1,%2,%3};"
        : "+f"(d[0]), "+f"(d[1]), "+f"(d[2]), "+f"(d[3])
        : "r"(a[0]), "r"(a[1]), "r"(a[2]), "r"(a[3]), "r"(b[0]), "r"(b[1]));
}

__global__ __launch_bounds__(256, 2) void gemm_tc(const float* __restrict__ A,
                                                  const float* __restrict__ Bm,
                                                  float* __restrict__ C,
                                                  int M, int N, int K)
{
    __shared__ float Ahi[BM][LDS_STRIDE];
    __shared__ float Alo[BM][LDS_STRIDE];
    __shared__ float Bhi[BN][LDS_STRIDE];
    __shared__ float Blo[BN][LDS_STRIDE];

    const int tid  = threadIdx.x;
    const int warp = tid >> 5;
    const int lane = tid & 31;
    const int m0 = blockIdx.y * BM;
    const int n0 = blockIdx.x * BN;

    const int wm = (warp >> 1) * 32;   // warp M offset: 0,32,64,96
    const int wn = (warp & 1) * 64;    // warp N offset: 0,64
    const int g  = lane >> 2;          // 0..7
    const int t4 = lane & 3;           // 0..3

    // global load mapping: 4 iters, each covers 32 rows x 8 float4 (=32 k)
    const int lrow = tid >> 3;         // 0..31
    const int lkq  = (tid & 7) * 4;    // 0,4,...,28

    float acc[2][8][4];
#pragma unroll
    for (int mf = 0; mf < 2; mf++)
#pragma unroll
        for (int nf = 0; nf < 8; nf++)
#pragma unroll
            for (int r = 0; r < 4; r++) acc[mf][nf][r] = 0.0f;

    for (int k0 = 0; k0 < K; k0 += BK) {
        if (k0) __syncthreads();

        // Fill smem: split each fp32 into tf32 hi + tf32 lo
#pragma unroll
        for (int i = 0; i < 4; i++) {
            const int row = lrow + i * 32;
            float4 av = *(const float4*)(A + (size_t)(m0 + row) * K + k0 + lkq);
            float4 bv = *(const float4*)(Bm + (size_t)(n0 + row) * K + k0 + lkq);

            float4 ah, al, bh, bl;
            {
                uint32_t h;
                h = f2tf32(av.x); ah.x = __uint_as_float(h); al.x = __uint_as_float(f2tf32(av.x - ah.x));
                h = f2tf32(av.y); ah.y = __uint_as_float(h); al.y = __uint_as_float(f2tf32(av.y - ah.y));
                h = f2tf32(av.z); ah.z = __uint_as_float(h); al.z = __uint_as_float(f2tf32(av.z - ah.z));
                h = f2tf32(av.w); ah.w = __uint_as_float(h); al.w = __uint_as_float(f2tf32(av.w - ah.w));
                h = f2tf32(bv.x); bh.x = __uint_as_float(h); bl.x = __uint_as_float(f2tf32(bv.x - bh.x));
                h = f2tf32(bv.y); bh.y = __uint_as_float(h); bl.y = __uint_as_float(f2tf32(bv.y - bh.y));
                h = f2tf32(bv.z); bh.z = __uint_as_float(h); bl.z = __uint_as_float(f2tf32(bv.z - bh.z));
                h = f2tf32(bv.w); bh.w = __uint_as_float(h); bl.w = __uint_as_float(f2tf32(bv.w - bh.w));
            }
            *(float4*)&Ahi[row][lkq] = ah;
            *(float4*)&Alo[row][lkq] = al;
            *(float4*)&Bhi[row][lkq] = bh;
            *(float4*)&Blo[row][lkq] = bl;
        }
        __syncthreads();

#pragma unroll
        for (int ks = 0; ks < 4; ks++) {
            const int k = ks * 8;

            uint32_t ahi[2][4], alo[2][4];
#pragma unroll
            for (int mf = 0; mf < 2; mf++) {
                const int r = wm + mf * 16 + g;
                ahi[mf][0] = __float_as_uint(Ahi[r][k + t4]);
                ahi[mf][1] = __float_as_uint(Ahi[r + 8][k + t4]);
                ahi[mf][2] = __float_as_uint(Ahi[r][k + t4 + 4]);
                ahi[mf][3] = __float_as_uint(Ahi[r + 8][k + t4 + 4]);
                alo[mf][0] = __float_as_uint(Alo[r][k + t4]);
                alo[mf][1] = __float_as_uint(Alo[r + 8][k + t4]);
                alo[mf][2] = __float_as_uint(Alo[r][k + t4 + 4]);
                alo[mf][3] = __float_as_uint(Alo[r + 8][k + t4 + 4]);
            }

#pragma unroll
            for (int nf = 0; nf < 8; nf++) {
                const int c = wn + nf * 8 + g;
                uint32_t bh[2], bl[2];
                bh[0] = __float_as_uint(Bhi[c][k + t4]);
                bh[1] = __float_as_uint(Bhi[c][k + t4 + 4]);
                bl[0] = __float_as_uint(Blo[c][k + t4]);
                bl[1] = __float_as_uint(Blo[c][k + t4 + 4]);
#pragma unroll
                for (int mf = 0; mf < 2; mf++) {
                    mma_tf32(acc[mf][nf], ahi[mf], bh);
                    mma_tf32(acc[mf][nf], alo[mf], bh);
                    mma_tf32(acc[mf][nf], ahi[mf], bl);
                }
            }
        }
    }

    // Epilogue: c0/c1 at (row, 2*t4), c2/c3 at (row+8, 2*t4)
#pragma unroll
    for (int mf = 0; mf < 2; mf++) {
#pragma unroll
        for (int nf = 0; nf < 8; nf++) {
            const int r = m0 + wm + mf * 16 + g;
            const int c = n0 + wn + nf * 8 + 2 * t4;
            float2 v0 = {acc[mf][nf][0], acc[mf][nf][1]};
            float2 v1 = {acc[mf][nf][2], acc[mf][nf][3]};
            *(float2*)(C + (size_t)r * N + c)       = v0;
            *(float2*)(C + (size_t)(r + 8) * N + c) = v1;
        }
    }
}

// ---------------------------------------------------------------------------
// RoPE applied in-place to Q (heads 0..31) and K (heads 32..39) of g_qkv.
// ---------------------------------------------------------------------------
__global__ void rope_kernel(float* __restrict__ qkv,
                            const int* __restrict__ positions)
{
    const int total = ROWS * (NQ + NKV) * (HD / 2);
    int idx = blockIdx.x * blockDim.x + threadIdx.x;
    if (idx >= total) return;

    const int i   = idx % (HD / 2);                 // 0..47
    const int h   = (idx / (HD / 2)) % (NQ + NKV);  // 0..39
    const int row = idx / ((HD / 2) * (NQ + NKV));  // 0..4095

    const int pos = positions[row & (SEQ - 1)];
    const float e = (float)(2 * i) / (float)HD;
    const float inv_freq = expf(-e * 9.210340371976184f);
    const float ang = (float)pos * inv_freq;
    float s, c;
    sincosf(ang, &s, &c);

    float* base = qkv + (size_t)row * QKV_N + h * HD + i;
    const float t1 = base[0];
    const float t2 = base[HD / 2];
    base[0]      = t1 * c - t2 * s;
    base[HD / 2] = t2 * c + t1 * s;
}

// ---------------------------------------------------------------------------
// Causal GQA flash attention, fp32 (unchanged from R1).
// ---------------------------------------------------------------------------
#define ATTN_SMEM_FLOATS (96*64 + 96*64 + 64*96 + 64*65 + 3*64)
#define ATTN_SMEM_BYTES  (ATTN_SMEM_FLOATS * 4)

__global__ __launch_bounds__(256) void attn_kernel(const float* __restrict__ qkv,
                                                   float* __restrict__ out)
{
    extern __shared__ float sm[];
    float* Qs = sm;                 // [96][64]  k-major
    float* Ks = Qs + 96 * 64;       // [96][64]  k-major
    float* Vs = Ks + 96 * 64;       // [64][96]
    float* Ss = Vs + 64 * 96;       // [64][65]
    float* Ms = Ss + 64 * 65;
    float* Ls = Ms + 64;
    float* Cs = Ls + 64;

    const int qb  = blockIdx.x;
    const int qh  = blockIdx.y;
    const int bb  = blockIdx.z;
    const int kvh = qh >> 2;
    const int tid = threadIdx.x;
    const int ty = tid >> 4, tx = tid & 15;
    const int r0 = ty * 4;
    const int c0 = tx * 6;
    const float scale = 0.10206207261596577f;

    for (int idx = tid; idx < 64 * 96; idx += 256) {
        const int r = idx / 96, d = idx % 96;
        Qs[d * 64 + r] = qkv[(size_t)(bb * SEQ + qb * 64 + r) * QKV_N + qh * HD + d];
    }
    if (tid < 64) { Ms[tid] = -INFINITY; Ls[tid] = 0.0f; }

    float o[4][6];
#pragma unroll
    for (int i = 0; i < 4; i++)
#pragma unroll
        for (int c = 0; c < 6; c++) o[i][c] = 0.0f;

    for (int kb = 0; kb <= qb; kb++) {
        __syncthreads();

        for (int idx = tid; idx < 64 * 96; idx += 256) {
            const int r = idx / 96, d = idx % 96;
            const float* p = qkv + (size_t)(bb * SEQ + kb * 64 + r) * QKV_N + kvh * HD + d;
            Ks[d * 64 + r] = p[KOFF];
            Vs[r * 96 + d] = p[VOFF];
        }
        __syncthreads();

        float sa[4][4];
#pragma unroll
        for (int i = 0; i < 4; i++)
#pragma unroll
            for (int j = 0; j < 4; j++) sa[i][j] = 0.0f;

#pragma unroll 8
        for (int k = 0; k < 96; k++) {
            float4 qa = *(const float4*)&Qs[k * 64 + r0];
            float4 ka = *(const float4*)&Ks[k * 64 + tx * 4];
            float qf[4] = {qa.x, qa.y, qa.z, qa.w};
            float kf[4] = {ka.x, ka.y, ka.z, ka.w};
#pragma unroll
            for (int i = 0; i < 4; i++)
#pragma unroll
                for (int j = 0; j < 4; j++)
                    sa[i][j] = fmaf(qf[i], kf[j], sa[i][j]);
        }

#pragma unroll
        for (int i = 0; i < 4; i++) {
            const int qrow = qb * 64 + r0 + i;
#pragma unroll
            for (int j = 0; j < 4; j++) {
                const int kc = kb * 64 + tx * 4 + j;
                float v = sa[i][j] * scale;
                if (kc > qrow) v = -1e30f;
                Ss[(r0 + i) * 65 + tx * 4 + j] = v;
            }
        }
        __syncthreads();

        if (tid < 64) {
            const float mo = Ms[tid];
            float rm = mo;
            for (int j = 0; j < 64; j++) rm = fmaxf(rm, Ss[tid * 65 + j]);
            const float co = __expf(mo - rm);
            float l = Ls[tid] * co;
            for (int j = 0; j < 64; j++) {
                const float p = __expf(Ss[tid * 65 + j] - rm);
                Ss[tid * 65 + j] = p;
                l += p;
            }
            Ms[tid] = rm; Ls[tid] = l; Cs[tid] = co;
        }
        __syncthreads();

        float cf[4];
#pragma unroll
        for (int i = 0; i < 4; i++) {
            cf[i] = Cs[r0 + i];
#pragma unroll
            for (int c = 0; c < 6; c++) o[i][c] *= cf[i];
        }
#pragma unroll 4
        for (int j = 0; j < 64; j++) {
            float p0 = Ss[(r0 + 0) * 65 + j];
            float p1 = Ss[(r0 + 1) * 65 + j];
            float p2 = Ss[(r0 + 2) * 65 + j];
            float p3 = Ss[(r0 + 3) * 65 + j];
            float2 v0 = *(const float2*)&Vs[j * 96 + c0];
            float2 v1 = *(const float2*)&Vs[j * 96 + c0 + 2];
            float2 v2 = *(const float2*)&Vs[j * 96 + c0 + 4];
            float vf[6] = {v0.x, v0.y, v1.x, v1.y, v2.x, v2.y};
            float pf[4] = {p0, p1, p2, p3};
#pragma unroll
            for (int i = 0; i < 4; i++)
#pragma unroll
                for (int c = 0; c < 6; c++)
                    o[i][c] = fmaf(pf[i], vf[c], o[i][c]);
        }
    }

#pragma unroll
    for (int i = 0; i < 4; i++) {
        const float inv_l = 1.0f / Ls[r0 + i];
        float* orow = out + (size_t)(bb * SEQ + qb * 64 + r0 + i) * EMBED + qh * HD + c0;
#pragma unroll
        for (int c = 0; c < 6; c++) orow[c] = o[i][c] * inv_l;
    }
}

// ---------------------------------------------------------------------------
// Launch
// ---------------------------------------------------------------------------
extern "C" void kernel_launch(void* const* d_in, const int* in_sizes, int n_in,
                              void* d_out, int out_size)
{
    const float* x         = (const float*)d_in[0];
    const int*   positions = (const int*)d_in[1];
    const float* W_qkv     = (const float*)d_in[3];
    const float* W_o       = (const float*)d_in[4];
    float* out = (float*)d_out;

    float* qkv;  cudaGetSymbolAddress((void**)&qkv,  g_qkv);
    float* attn; cudaGetSymbolAddress((void**)&attn, g_attn);

    cudaFuncSetAttribute(attn_kernel,
                         cudaFuncAttributeMaxDynamicSharedMemorySize,
                         ATTN_SMEM_BYTES);

    // 1) QKV projection (tf32 tensor cores, 3xTF32 compensated)
    gemm_tc<<<dim3(QKV_N / 128, ROWS / 128), 256>>>(x, W_qkv, qkv,
                                                    ROWS, QKV_N, EMBED);

    // 2) RoPE on Q and K in place
    {
        const int total = ROWS * (NQ + NKV) * (HD / 2);
        rope_kernel<<<(total + 255) / 256, 256>>>(qkv, positions);
    }

    // 3) Causal GQA attention
    attn_kernel<<<dim3(SEQ / 64, NQ, BATCH), 256, ATTN_SMEM_BYTES>>>(qkv, attn);

    // 4) Output projection (tf32 tensor cores)
    gemm_tc<<<dim3(EMBED / 128, ROWS / 128), 256>>>(attn, W_o, out,
                                                    ROWS, EMBED, EMBED);
}

// round 7
// speedup vs baseline: 1.7088x; 1.2607x over previous
#include <cuda_runtime.h>
#include <cuda_bf16.h>
#include <math.h>
#include <stdint.h>

#define EMBED 3072
#define NQ 32
#define NKV 8
#define HD 96
#define BATCH 2
#define SEQ 2048
#define ROWS (BATCH*SEQ)                 // 4096
#define QKV_N (NQ*HD + 2*NKV*HD)         // 4608
#define KOFF (NQ*HD)                     // 3072
#define VOFF (NQ*HD + NKV*HD)            // 3840
#define GROUPS (NQ/NKV)                  // 4

// Scratch (allocation-free rule: __device__ globals)
__device__ float g_qkv[ROWS * QKV_N];    // ~75.5 MB
__device__ float g_attn[ROWS * EMBED];   // ~50.3 MB

// ---------------------------------------------------------------------------
// BF16 tensor-core GEMM with 3-term split-precision compensation.
// C[M,N] = A[M,K] * B[N,K]^T  (both row-major, K contiguous).
// CTA tile 128x128, BK=32, 8 warps (4x2), warp tile 32x64.
// mma.sync.aligned.m16n8k16.row.col.f32.bf16.bf16.f32
// x = hi + mid (+eps); C ~= Ahi*Bhi + Amid*Bhi + Ahi*Bmid  (err ~2^-16)
// ---------------------------------------------------------------------------
#define BM 128
#define BN 128
#define BK 32
#define SB 40   // smem row stride in bf16 elems (BK + 8) -> conflict-free

__device__ __forceinline__ void mma_bf16(float* d, const uint32_t* a, const uint32_t* b) {
    asm volatile(
        "mma.sync.aligned.m16n8k16.row.col.f32.bf16.bf16.f32 "
        "{%0,%1,%2,%3}, {%4,%5,%6,%7}, {%8,%9}, {%0,%1,%2,%3};"
        : "+f"(d[0]), "+f"(d[1]), "+f"(d[2]), "+f"(d[3])
        : "r"(a[0]), "r"(a[1]), "r"(a[2]), "r"(a[3]), "r"(b[0]), "r"(b[1]));
}

// pack two floats into a bf16x2 hi word and a bf16x2 mid word
__device__ __forceinline__ void split2(float x, float y, uint32_t& hi, uint32_t& mid) {
    __nv_bfloat16 hx = __float2bfloat16(x);
    __nv_bfloat16 hy = __float2bfloat16(y);
    __nv_bfloat16 mx = __float2bfloat16(x - __bfloat162float(hx));
    __nv_bfloat16 my = __float2bfloat16(y - __bfloat162float(hy));
    hi  = ((uint32_t)__bfloat16_as_ushort(hy) << 16) | __bfloat16_as_ushort(hx);
    mid = ((uint32_t)__bfloat16_as_ushort(my) << 16) | __bfloat16_as_ushort(mx);
}

__global__ __launch_bounds__(256, 2) void gemm_tc(const float* __restrict__ A,
                                                  const float* __restrict__ Bm,
                                                  float* __restrict__ C,
                                                  int M, int N, int K)
{
    __shared__ __nv_bfloat16 Ahi[BM][SB];
    __shared__ __nv_bfloat16 Ami[BM][SB];
    __shared__ __nv_bfloat16 Bhi[BN][SB];
    __shared__ __nv_bfloat16 Bmi[BN][SB];

    const int tid  = threadIdx.x;
    const int warp = tid >> 5;
    const int lane = tid & 31;
    const int m0 = blockIdx.y * BM;
    const int n0 = blockIdx.x * BN;

    const int wm = (warp >> 1) * 32;   // warp M offset: 0,32,64,96
    const int wn = (warp & 1) * 64;    // warp N offset: 0,64
    const int g  = lane >> 2;          // 0..7
    const int t4 = lane & 3;           // 0..3

    // global load mapping: 4 iters, each covers 32 rows x 8 float4 (=32 k)
    const int lrow = tid >> 3;         // 0..31
    const int lkq  = (tid & 7) * 4;    // 0,4,...,28

    float acc[2][8][4];
#pragma unroll
    for (int mf = 0; mf < 2; mf++)
#pragma unroll
        for (int nf = 0; nf < 8; nf++)
#pragma unroll
            for (int r = 0; r < 4; r++) acc[mf][nf][r] = 0.0f;

    for (int k0 = 0; k0 < K; k0 += BK) {
        if (k0) __syncthreads();

        // Fill smem: split each fp32 into bf16 hi + bf16 mid
#pragma unroll
        for (int i = 0; i < 4; i++) {
            const int row = lrow + i * 32;
            float4 av = *(const float4*)(A + (size_t)(m0 + row) * K + k0 + lkq);
            float4 bv = *(const float4*)(Bm + (size_t)(n0 + row) * K + k0 + lkq);

            uint2 ah, am, bh, bm;
            split2(av.x, av.y, ah.x, am.x);
            split2(av.z, av.w, ah.y, am.y);
            split2(bv.x, bv.y, bh.x, bm.x);
            split2(bv.z, bv.w, bh.y, bm.y);

            *(uint2*)&Ahi[row][lkq] = ah;
            *(uint2*)&Ami[row][lkq] = am;
            *(uint2*)&Bhi[row][lkq] = bh;
            *(uint2*)&Bmi[row][lkq] = bm;
        }
        __syncthreads();

#pragma unroll
        for (int ks = 0; ks < 2; ks++) {
            const int k = ks * 16;
            const int kk = k + 2 * t4;

            uint32_t ahi[2][4], ami[2][4];
#pragma unroll
            for (int mf = 0; mf < 2; mf++) {
                const int r = wm + mf * 16 + g;
                ahi[mf][0] = *(const uint32_t*)&Ahi[r][kk];
                ahi[mf][1] = *(const uint32_t*)&Ahi[r + 8][kk];
                ahi[mf][2] = *(const uint32_t*)&Ahi[r][kk + 8];
                ahi[mf][3] = *(const uint32_t*)&Ahi[r + 8][kk + 8];
                ami[mf][0] = *(const uint32_t*)&Ami[r][kk];
                ami[mf][1] = *(const uint32_t*)&Ami[r + 8][kk];
                ami[mf][2] = *(const uint32_t*)&Ami[r][kk + 8];
                ami[mf][3] = *(const uint32_t*)&Ami[r + 8][kk + 8];
            }

#pragma unroll
            for (int nf = 0; nf < 8; nf++) {
                const int c = wn + nf * 8 + g;
                uint32_t bh[2], bm_[2];
                bh[0]  = *(const uint32_t*)&Bhi[c][kk];
                bh[1]  = *(const uint32_t*)&Bhi[c][kk + 8];
                bm_[0] = *(const uint32_t*)&Bmi[c][kk];
                bm_[1] = *(const uint32_t*)&Bmi[c][kk + 8];
#pragma unroll
                for (int mf = 0; mf < 2; mf++) {
                    mma_bf16(acc[mf][nf], ahi[mf], bh);
                    mma_bf16(acc[mf][nf], ami[mf], bh);
                    mma_bf16(acc[mf][nf], ahi[mf], bm_);
                }
            }
        }
    }

    // Epilogue: c0/c1 at (row, 2*t4), c2/c3 at (row+8, 2*t4)
#pragma unroll
    for (int mf = 0; mf < 2; mf++) {
#pragma unroll
        for (int nf = 0; nf < 8; nf++) {
            const int r = m0 + wm + mf * 16 + g;
            const int c = n0 + wn + nf * 8 + 2 * t4;
            float2 v0 = {acc[mf][nf][0], acc[mf][nf][1]};
            float2 v1 = {acc[mf][nf][2], acc[mf][nf][3]};
            *(float2*)(C + (size_t)r * N + c)       = v0;
            *(float2*)(C + (size_t)(r + 8) * N + c) = v1;
        }
    }
}

// ---------------------------------------------------------------------------
// RoPE applied in-place to Q (heads 0..31) and K (heads 32..39) of g_qkv.
// ---------------------------------------------------------------------------
__global__ void rope_kernel(float* __restrict__ qkv,
                            const int* __restrict__ positions)
{
    const int total = ROWS * (NQ + NKV) * (HD / 2);
    int idx = blockIdx.x * blockDim.x + threadIdx.x;
    if (idx >= total) return;

    const int i   = idx % (HD / 2);                 // 0..47
    const int h   = (idx / (HD / 2)) % (NQ + NKV);  // 0..39
    const int row = idx / ((HD / 2) * (NQ + NKV));  // 0..4095

    const int pos = positions[row & (SEQ - 1)];
    const float e = (float)(2 * i) / (float)HD;
    const float inv_freq = expf(-e * 9.210340371976184f);
    const float ang = (float)pos * inv_freq;
    float s, c;
    sincosf(ang, &s, &c);

    float* base = qkv + (size_t)row * QKV_N + h * HD + i;
    const float t1 = base[0];
    const float t2 = base[HD / 2];
    base[0]      = t1 * c - t2 * s;
    base[HD / 2] = t2 * c + t1 * s;
}

// ---------------------------------------------------------------------------
// Causal GQA flash attention, fp32 (unchanged).
// ---------------------------------------------------------------------------
#define ATTN_SMEM_FLOATS (96*64 + 96*64 + 64*96 + 64*65 + 3*64)
#define ATTN_SMEM_BYTES  (ATTN_SMEM_FLOATS * 4)

__global__ __launch_bounds__(256) void attn_kernel(const float* __restrict__ qkv,
                                                   float* __restrict__ out)
{
    extern __shared__ float sm[];
    float* Qs = sm;                 // [96][64]  k-major
    float* Ks = Qs + 96 * 64;       // [96][64]  k-major
    float* Vs = Ks + 96 * 64;       // [64][96]
    float* Ss = Vs + 64 * 96;       // [64][65]
    float* Ms = Ss + 64 * 65;
    float* Ls = Ms + 64;
    float* Cs = Ls + 64;

    const int qb  = blockIdx.x;
    const int qh  = blockIdx.y;
    const int bb  = blockIdx.z;
    const int kvh = qh >> 2;
    const int tid = threadIdx.x;
    const int ty = tid >> 4, tx = tid & 15;
    const int r0 = ty * 4;
    const int c0 = tx * 6;
    const float scale = 0.10206207261596577f;

    for (int idx = tid; idx < 64 * 96; idx += 256) {
        const int r = idx / 96, d = idx % 96;
        Qs[d * 64 + r] = qkv[(size_t)(bb * SEQ + qb * 64 + r) * QKV_N + qh * HD + d];
    }
    if (tid < 64) { Ms[tid] = -INFINITY; Ls[tid] = 0.0f; }

    float o[4][6];
#pragma unroll
    for (int i = 0; i < 4; i++)
#pragma unroll
        for (int c = 0; c < 6; c++) o[i][c] = 0.0f;

    for (int kb = 0; kb <= qb; kb++) {
        __syncthreads();

        for (int idx = tid; idx < 64 * 96; idx += 256) {
            const int r = idx / 96, d = idx % 96;
            const float* p = qkv + (size_t)(bb * SEQ + kb * 64 + r) * QKV_N + kvh * HD + d;
            Ks[d * 64 + r] = p[KOFF];
            Vs[r * 96 + d] = p[VOFF];
        }
        __syncthreads();

        float sa[4][4];
#pragma unroll
        for (int i = 0; i < 4; i++)
#pragma unroll
            for (int j = 0; j < 4; j++) sa[i][j] = 0.0f;

#pragma unroll 8
        for (int k = 0; k < 96; k++) {
            float4 qa = *(const float4*)&Qs[k * 64 + r0];
            float4 ka = *(const float4*)&Ks[k * 64 + tx * 4];
            float qf[4] = {qa.x, qa.y, qa.z, qa.w};
            float kf[4] = {ka.x, ka.y, ka.z, ka.w};
#pragma unroll
            for (int i = 0; i < 4; i++)
#pragma unroll
                for (int j = 0; j < 4; j++)
                    sa[i][j] = fmaf(qf[i], kf[j], sa[i][j]);
        }

#pragma unroll
        for (int i = 0; i < 4; i++) {
            const int qrow = qb * 64 + r0 + i;
#pragma unroll
            for (int j = 0; j < 4; j++) {
                const int kc = kb * 64 + tx * 4 + j;
                float v = sa[i][j] * scale;
                if (kc > qrow) v = -1e30f;
                Ss[(r0 + i) * 65 + tx * 4 + j] = v;
            }
        }
        __syncthreads();

        if (tid < 64) {
            const float mo = Ms[tid];
            float rm = mo;
            for (int j = 0; j < 64; j++) rm = fmaxf(rm, Ss[tid * 65 + j]);
            const float co = __expf(mo - rm);
            float l = Ls[tid] * co;
            for (int j = 0; j < 64; j++) {
                const float p = __expf(Ss[tid * 65 + j] - rm);
                Ss[tid * 65 + j] = p;
                l += p;
            }
            Ms[tid] = rm; Ls[tid] = l; Cs[tid] = co;
        }
        __syncthreads();

        float cf[4];
#pragma unroll
        for (int i = 0; i < 4; i++) {
            cf[i] = Cs[r0 + i];
#pragma unroll
            for (int c = 0; c < 6; c++) o[i][c] *= cf[i];
        }
#pragma unroll 4
        for (int j = 0; j < 64; j++) {
            float p0 = Ss[(r0 + 0) * 65 + j];
            float p1 = Ss[(r0 + 1) * 65 + j];
            float p2 = Ss[(r0 + 2) * 65 + j];
            float p3 = Ss[(r0 + 3) * 65 + j];
            float2 v0 = *(const float2*)&Vs[j * 96 + c0];
            float2 v1 = *(const float2*)&Vs[j * 96 + c0 + 2];
            float2 v2 = *(const float2*)&Vs[j * 96 + c0 + 4];
            float vf[6] = {v0.x, v0.y, v1.x, v1.y, v2.x, v2.y};
            float pf[4] = {p0, p1, p2, p3};
#pragma unroll
            for (int i = 0; i < 4; i++)
#pragma unroll
                for (int c = 0; c < 6; c++)
                    o[i][c] = fmaf(pf[i], vf[c], o[i][c]);
        }
    }

#pragma unroll
    for (int i = 0; i < 4; i++) {
        const float inv_l = 1.0f / Ls[r0 + i];
        float* orow = out + (size_t)(bb * SEQ + qb * 64 + r0 + i) * EMBED + qh * HD + c0;
#pragma unroll
        for (int c = 0; c < 6; c++) orow[c] = o[i][c] * inv_l;
    }
}

// ---------------------------------------------------------------------------
// Launch
// ---------------------------------------------------------------------------
extern "C" void kernel_launch(void* const* d_in, const int* in_sizes, int n_in,
                              void* d_out, int out_size)
{
    const float* x         = (const float*)d_in[0];
    const int*   positions = (const int*)d_in[1];
    const float* W_qkv     = (const float*)d_in[3];
    const float* W_o       = (const float*)d_in[4];
    float* out = (float*)d_out;

    float* qkv;  cudaGetSymbolAddress((void**)&qkv,  g_qkv);
    float* attn; cudaGetSymbolAddress((void**)&attn, g_attn);

    cudaFuncSetAttribute(attn_kernel,
                         cudaFuncAttributeMaxDynamicSharedMemorySize,
                         ATTN_SMEM_BYTES);

    // 1) QKV projection (bf16 tensor cores, 3-term split)
    gemm_tc<<<dim3(QKV_N / 128, ROWS / 128), 256>>>(x, W_qkv, qkv,
                                                    ROWS, QKV_N, EMBED);

    // 2) RoPE on Q and K in place
    {
        const int total = ROWS * (NQ + NKV) * (HD / 2);
        rope_kernel<<<(total + 255) / 256, 256>>>(qkv, positions);
    }

    // 3) Causal GQA attention
    attn_kernel<<<dim3(SEQ / 64, NQ, BATCH), 256, ATTN_SMEM_BYTES>>>(qkv, attn);

    // 4) Output projection (bf16 tensor cores, 3-term split)
    gemm_tc<<<dim3(EMBED / 128, ROWS / 128), 256>>>(attn, W_o, out,
                                                    ROWS, EMBED, EMBED);
}

// round 9
// speedup vs baseline: 2.3547x; 1.3780x over previous
#include <cuda_runtime.h>
#include <cuda_bf16.h>
#include <math.h>
#include <stdint.h>

#define EMBED 3072
#define NQ 32
#define NKV 8
#define HD 96
#define BATCH 2
#define SEQ 2048
#define ROWS (BATCH*SEQ)                 // 4096
#define QKV_N (NQ*HD + 2*NKV*HD)         // 4608
#define KOFF (NQ*HD)                     // 3072
#define VOFF (NQ*HD + NKV*HD)            // 3840
#define GROUPS (NQ/NKV)                  // 4

// Scratch (allocation-free rule: __device__ globals)
__device__ float g_qkv[ROWS * QKV_N];    // ~75.5 MB
__device__ float g_attn[ROWS * EMBED];   // ~50.3 MB

// ---------------------------------------------------------------------------
// Common helpers
// ---------------------------------------------------------------------------
__device__ __forceinline__ void mma_bf16(float* d, const uint32_t* a, const uint32_t* b) {
    asm volatile(
        "mma.sync.aligned.m16n8k16.row.col.f32.bf16.bf16.f32 "
        "{%0,%1,%2,%3}, {%4,%5,%6,%7}, {%8,%9}, {%0,%1,%2,%3};"
        : "+f"(d[0]), "+f"(d[1]), "+f"(d[2]), "+f"(d[3])
        : "r"(a[0]), "r"(a[1]), "r"(a[2]), "r"(a[3]), "r"(b[0]), "r"(b[1]));
}

// pack two floats into a bf16x2 hi word and a bf16x2 mid word
__device__ __forceinline__ void split2(float x, float y, uint32_t& hi, uint32_t& mid) {
    __nv_bfloat16 hx = __float2bfloat16(x);
    __nv_bfloat16 hy = __float2bfloat16(y);
    __nv_bfloat16 mx = __float2bfloat16(x - __bfloat162float(hx));
    __nv_bfloat16 my = __float2bfloat16(y - __bfloat162float(hy));
    hi  = ((uint32_t)__bfloat16_as_ushort(hy) << 16) | __bfloat16_as_ushort(hx);
    mid = ((uint32_t)__bfloat16_as_ushort(my) << 16) | __bfloat16_as_ushort(mx);
}

// ---------------------------------------------------------------------------
// BF16 tensor-core GEMM with 3-term split-precision compensation (unchanged).
// C[M,N] = A[M,K] * B[N,K]^T.  CTA 128x128, BK=32, 8 warps, warp tile 32x64.
// ---------------------------------------------------------------------------
#define BM 128
#define BN 128
#define BK 32
#define SB 40   // smem row stride in bf16 elems

__global__ __launch_bounds__(256, 2) void gemm_tc(const float* __restrict__ A,
                                                  const float* __restrict__ Bm,
                                                  float* __restrict__ C,
                                                  int M, int N, int K)
{
    __shared__ __nv_bfloat16 Ahi[BM][SB];
    __shared__ __nv_bfloat16 Ami[BM][SB];
    __shared__ __nv_bfloat16 Bhi[BN][SB];
    __shared__ __nv_bfloat16 Bmi[BN][SB];

    const int tid  = threadIdx.x;
    const int warp = tid >> 5;
    const int lane = tid & 31;
    const int m0 = blockIdx.y * BM;
    const int n0 = blockIdx.x * BN;

    const int wm = (warp >> 1) * 32;
    const int wn = (warp & 1) * 64;
    const int g  = lane >> 2;
    const int t4 = lane & 3;

    const int lrow = tid >> 3;
    const int lkq  = (tid & 7) * 4;

    float acc[2][8][4];
#pragma unroll
    for (int mf = 0; mf < 2; mf++)
#pragma unroll
        for (int nf = 0; nf < 8; nf++)
#pragma unroll
            for (int r = 0; r < 4; r++) acc[mf][nf][r] = 0.0f;

    for (int k0 = 0; k0 < K; k0 += BK) {
        if (k0) __syncthreads();

#pragma unroll
        for (int i = 0; i < 4; i++) {
            const int row = lrow + i * 32;
            float4 av = *(const float4*)(A + (size_t)(m0 + row) * K + k0 + lkq);
            float4 bv = *(const float4*)(Bm + (size_t)(n0 + row) * K + k0 + lkq);

            uint2 ah, am, bh, bm;
            split2(av.x, av.y, ah.x, am.x);
            split2(av.z, av.w, ah.y, am.y);
            split2(bv.x, bv.y, bh.x, bm.x);
            split2(bv.z, bv.w, bh.y, bm.y);

            *(uint2*)&Ahi[row][lkq] = ah;
            *(uint2*)&Ami[row][lkq] = am;
            *(uint2*)&Bhi[row][lkq] = bh;
            *(uint2*)&Bmi[row][lkq] = bm;
        }
        __syncthreads();

#pragma unroll
        for (int ks = 0; ks < 2; ks++) {
            const int kk = ks * 16 + 2 * t4;

            uint32_t ahi[2][4], ami[2][4];
#pragma unroll
            for (int mf = 0; mf < 2; mf++) {
                const int r = wm + mf * 16 + g;
                ahi[mf][0] = *(const uint32_t*)&Ahi[r][kk];
                ahi[mf][1] = *(const uint32_t*)&Ahi[r + 8][kk];
                ahi[mf][2] = *(const uint32_t*)&Ahi[r][kk + 8];
                ahi[mf][3] = *(const uint32_t*)&Ahi[r + 8][kk + 8];
                ami[mf][0] = *(const uint32_t*)&Ami[r][kk];
                ami[mf][1] = *(const uint32_t*)&Ami[r + 8][kk];
                ami[mf][2] = *(const uint32_t*)&Ami[r][kk + 8];
                ami[mf][3] = *(const uint32_t*)&Ami[r + 8][kk + 8];
            }

#pragma unroll
            for (int nf = 0; nf < 8; nf++) {
                const int c = wn + nf * 8 + g;
                uint32_t bh[2], bm_[2];
                bh[0]  = *(const uint32_t*)&Bhi[c][kk];
                bh[1]  = *(const uint32_t*)&Bhi[c][kk + 8];
                bm_[0] = *(const uint32_t*)&Bmi[c][kk];
                bm_[1] = *(const uint32_t*)&Bmi[c][kk + 8];
#pragma unroll
                for (int mf = 0; mf < 2; mf++) {
                    mma_bf16(acc[mf][nf], ahi[mf], bh);
                    mma_bf16(acc[mf][nf], ami[mf], bh);
                    mma_bf16(acc[mf][nf], ahi[mf], bm_);
                }
            }
        }
    }

#pragma unroll
    for (int mf = 0; mf < 2; mf++) {
#pragma unroll
        for (int nf = 0; nf < 8; nf++) {
            const int r = m0 + wm + mf * 16 + g;
            const int c = n0 + wn + nf * 8 + 2 * t4;
            float2 v0 = {acc[mf][nf][0], acc[mf][nf][1]};
            float2 v1 = {acc[mf][nf][2], acc[mf][nf][3]};
            *(float2*)(C + (size_t)r * N + c)       = v0;
            *(float2*)(C + (size_t)(r + 8) * N + c) = v1;
        }
    }
}

// ---------------------------------------------------------------------------
// RoPE applied in-place to Q (heads 0..31) and K (heads 32..39) of g_qkv.
// ---------------------------------------------------------------------------
__global__ void rope_kernel(float* __restrict__ qkv,
                            const int* __restrict__ positions)
{
    const int total = ROWS * (NQ + NKV) * (HD / 2);
    int idx = blockIdx.x * blockDim.x + threadIdx.x;
    if (idx >= total) return;

    const int i   = idx % (HD / 2);
    const int h   = (idx / (HD / 2)) % (NQ + NKV);
    const int row = idx / ((HD / 2) * (NQ + NKV));

    const int pos = positions[row & (SEQ - 1)];
    const float e = (float)(2 * i) / (float)HD;
    const float inv_freq = expf(-e * 9.210340371976184f);
    const float ang = (float)pos * inv_freq;
    float s, c;
    sincosf(ang, &s, &c);

    float* base = qkv + (size_t)row * QKV_N + h * HD + i;
    const float t1 = base[0];
    const float t2 = base[HD / 2];
    base[0]      = t1 * c - t2 * s;
    base[HD / 2] = t2 * c + t1 * s;
}

// ---------------------------------------------------------------------------
// Causal GQA flash attention with bf16 MMA + 3-term split precision.
// CTA = 64 q-rows for one (head, batch). 8 warps in 4x2 grid.
// S: warp tile 16x32 (K=96, 6 k-steps). PV: warp tile 16x48 (K=64, 4 k-steps).
// Register-resident online softmax; cross-warp row reduction via 128-f32 smem.
// Smem strides: Q/K 104 bf16 (bank = 20g+t4, conflict-free),
//               V/P 72 bf16 (bank = 4g+t4, conflict-free).
// ---------------------------------------------------------------------------
#define AQS 104   // Q/K row stride (bf16)
#define AVS 72    // V/P row stride (bf16)

#define ATTN_SM_BYTES ((4*64*AQS + 2*96*AVS + 2*64*AVS) * 2 + 2 * 128 * 4)

__global__ __launch_bounds__(256, 2) void attn_mma(const float* __restrict__ qkv,
                                                   float* __restrict__ out)
{
    extern __shared__ char sm_raw[];
    __nv_bfloat16* Qhi = (__nv_bfloat16*)sm_raw;
    __nv_bfloat16* Qmi = Qhi + 64 * AQS;
    __nv_bfloat16* Khi = Qmi + 64 * AQS;
    __nv_bfloat16* Kmi = Khi + 64 * AQS;
    __nv_bfloat16* Vhi = Kmi + 64 * AQS;
    __nv_bfloat16* Vmi = Vhi + 96 * AVS;
    __nv_bfloat16* Phi = Vmi + 96 * AVS;
    __nv_bfloat16* Pmi = Phi + 64 * AVS;
    float* redM = (float*)(Pmi + 64 * AVS);   // [2][64]
    float* redL = redM + 128;                 // [2][64]

    const int qb = blockIdx.x;   // 0..31 (64-row q block)
    const int qh = blockIdx.y;   // 0..31
    const int bb = blockIdx.z;   // 0..1
    const int kvh = qh >> 2;
    const int tid = threadIdx.x, warp = tid >> 5, lane = tid & 31;
    const int wy = warp >> 1, wx = warp & 1;
    const int g = lane >> 2, t4 = lane & 3;
    const int r0 = wy * 16 + g, r1 = r0 + 8;
    const float scale = 0.10206207261596577f;   // 96^-0.5

    // ---- load + split Q (64 x 96) ----
    for (int idx = tid; idx < 1536; idx += 256) {
        const int r = idx / 24, d = (idx % 24) * 4;
        float4 v = *(const float4*)(qkv + (size_t)(bb * SEQ + qb * 64 + r) * QKV_N + qh * HD + d);
        uint2 h, m;
        split2(v.x, v.y, h.x, m.x);
        split2(v.z, v.w, h.y, m.y);
        *(uint2*)&Qhi[r * AQS + d] = h;
        *(uint2*)&Qmi[r * AQS + d] = m;
    }

    float accO[6][4];
#pragma unroll
    for (int nf = 0; nf < 6; nf++)
#pragma unroll
        for (int e = 0; e < 4; e++) accO[nf][e] = 0.0f;
    float m_run0 = -1e30f, m_run1 = -1e30f, l_run0 = 0.0f, l_run1 = 0.0f;

    for (int kb = 0; kb <= qb; kb++) {
        __syncthreads();   // prev tile's MMAs/reductions done; Q ready (1st iter)

        // ---- load + split K and V (each 64 x 96); V stored transposed ----
        for (int idx = tid; idx < 1536; idx += 256) {
            const int r = idx / 24, d = (idx % 24) * 4;
            const float* p = qkv + (size_t)(bb * SEQ + kb * 64 + r) * QKV_N + kvh * HD + d;
            float4 kv = *(const float4*)(p + KOFF);
            float4 vv = *(const float4*)(p + VOFF);
            uint2 h, m;
            split2(kv.x, kv.y, h.x, m.x);
            split2(kv.z, kv.w, h.y, m.y);
            *(uint2*)&Khi[r * AQS + d] = h;
            *(uint2*)&Kmi[r * AQS + d] = m;
            float vs[4] = {vv.x, vv.y, vv.z, vv.w};
#pragma unroll
            for (int i = 0; i < 4; i++) {
                __nv_bfloat16 hb = __float2bfloat16(vs[i]);
                Vhi[(d + i) * AVS + r] = hb;
                Vmi[(d + i) * AVS + r] = __float2bfloat16(vs[i] - __bfloat162float(hb));
            }
        }
        __syncthreads();

        // ---- S = Q K^T  (64x64x96) ----
        float s[4][4];
#pragma unroll
        for (int nf = 0; nf < 4; nf++)
#pragma unroll
            for (int e = 0; e < 4; e++) s[nf][e] = 0.0f;

#pragma unroll
        for (int ks = 0; ks < 6; ks++) {
            const int kk = ks * 16 + 2 * t4;
            uint32_t ah[4], am[4];
            ah[0] = *(const uint32_t*)&Qhi[r0 * AQS + kk];
            ah[1] = *(const uint32_t*)&Qhi[r1 * AQS + kk];
            ah[2] = *(const uint32_t*)&Qhi[r0 * AQS + kk + 8];
            ah[3] = *(const uint32_t*)&Qhi[r1 * AQS + kk + 8];
            am[0] = *(const uint32_t*)&Qmi[r0 * AQS + kk];
            am[1] = *(const uint32_t*)&Qmi[r1 * AQS + kk];
            am[2] = *(const uint32_t*)&Qmi[r0 * AQS + kk + 8];
            am[3] = *(const uint32_t*)&Qmi[r1 * AQS + kk + 8];
#pragma unroll
            for (int nf = 0; nf < 4; nf++) {
                const int c = wx * 32 + nf * 8 + g;
                uint32_t bh[2], bm_[2];
                bh[0]  = *(const uint32_t*)&Khi[c * AQS + kk];
                bh[1]  = *(const uint32_t*)&Khi[c * AQS + kk + 8];
                bm_[0] = *(const uint32_t*)&Kmi[c * AQS + kk];
                bm_[1] = *(const uint32_t*)&Kmi[c * AQS + kk + 8];
                mma_bf16(s[nf], ah, bh);
                mma_bf16(s[nf], am, bh);
                mma_bf16(s[nf], ah, bm_);
            }
        }

        // ---- scale + causal mask ----
        const int rowg0 = qb * 64 + r0, rowg1 = qb * 64 + r1;
#pragma unroll
        for (int nf = 0; nf < 4; nf++) {
            const int cg = kb * 64 + wx * 32 + nf * 8 + 2 * t4;
            s[nf][0] = (cg     > rowg0) ? -1e30f : s[nf][0] * scale;
            s[nf][1] = (cg + 1 > rowg0) ? -1e30f : s[nf][1] * scale;
            s[nf][2] = (cg     > rowg1) ? -1e30f : s[nf][2] * scale;
            s[nf][3] = (cg + 1 > rowg1) ? -1e30f : s[nf][3] * scale;
        }

        // ---- row max: in-warp (t4 quad) then cross-warp via smem ----
        float mr0 = s[0][0], mr1 = s[0][2];
#pragma unroll
        for (int nf = 0; nf < 4; nf++) {
            mr0 = fmaxf(mr0, fmaxf(s[nf][0], s[nf][1]));
            mr1 = fmaxf(mr1, fmaxf(s[nf][2], s[nf][3]));
        }
        mr0 = fmaxf(mr0, __shfl_xor_sync(0xffffffffu, mr0, 1));
        mr0 = fmaxf(mr0, __shfl_xor_sync(0xffffffffu, mr0, 2));
        mr1 = fmaxf(mr1, __shfl_xor_sync(0xffffffffu, mr1, 1));
        mr1 = fmaxf(mr1, __shfl_xor_sync(0xffffffffu, mr1, 2));
        if (t4 == 0) {
            redM[wx * 64 + r0] = mr0;
            redM[wx * 64 + r1] = mr1;
        }
        __syncthreads();
        mr0 = fmaxf(mr0, redM[(1 - wx) * 64 + r0]);
        mr1 = fmaxf(mr1, redM[(1 - wx) * 64 + r1]);

        const float mn0 = fmaxf(m_run0, mr0), mn1 = fmaxf(m_run1, mr1);
        const float co0 = __expf(m_run0 - mn0), co1 = __expf(m_run1 - mn1);
        m_run0 = mn0; m_run1 = mn1;

        // ---- exp, row-sum, write split P ----
        float sum0 = 0.0f, sum1 = 0.0f;
#pragma unroll
        for (int nf = 0; nf < 4; nf++) {
            s[nf][0] = __expf(s[nf][0] - mn0);
            s[nf][1] = __expf(s[nf][1] - mn0);
            s[nf][2] = __expf(s[nf][2] - mn1);
            s[nf][3] = __expf(s[nf][3] - mn1);
            sum0 += s[nf][0] + s[nf][1];
            sum1 += s[nf][2] + s[nf][3];
            const int c = wx * 32 + nf * 8 + 2 * t4;
            uint32_t hw, mw;
            split2(s[nf][0], s[nf][1], hw, mw);
            *(uint32_t*)&Phi[r0 * AVS + c] = hw;
            *(uint32_t*)&Pmi[r0 * AVS + c] = mw;
            split2(s[nf][2], s[nf][3], hw, mw);
            *(uint32_t*)&Phi[r1 * AVS + c] = hw;
            *(uint32_t*)&Pmi[r1 * AVS + c] = mw;
        }
        sum0 += __shfl_xor_sync(0xffffffffu, sum0, 1);
        sum0 += __shfl_xor_sync(0xffffffffu, sum0, 2);
        sum1 += __shfl_xor_sync(0xffffffffu, sum1, 1);
        sum1 += __shfl_xor_sync(0xffffffffu, sum1, 2);
        if (t4 == 0) {
            redL[wx * 64 + r0] = sum0;
            redL[wx * 64 + r1] = sum1;
        }
        __syncthreads();   // redL + P visible
        l_run0 = l_run0 * co0 + redL[r0] + redL[64 + r0];
        l_run1 = l_run1 * co1 + redL[r1] + redL[64 + r1];

        // ---- rescale O, then O += P V ----
#pragma unroll
        for (int nf = 0; nf < 6; nf++) {
            accO[nf][0] *= co0; accO[nf][1] *= co0;
            accO[nf][2] *= co1; accO[nf][3] *= co1;
        }
#pragma unroll
        for (int ks = 0; ks < 4; ks++) {
            const int kk = ks * 16 + 2 * t4;
            uint32_t ah[4], am[4];
            ah[0] = *(const uint32_t*)&Phi[r0 * AVS + kk];
            ah[1] = *(const uint32_t*)&Phi[r1 * AVS + kk];
            ah[2] = *(const uint32_t*)&Phi[r0 * AVS + kk + 8];
            ah[3] = *(const uint32_t*)&Phi[r1 * AVS + kk + 8];
            am[0] = *(const uint32_t*)&Pmi[r0 * AVS + kk];
            am[1] = *(const uint32_t*)&Pmi[r1 * AVS + kk];
            am[2] = *(const uint32_t*)&Pmi[r0 * AVS + kk + 8];
            am[3] = *(const uint32_t*)&Pmi[r1 * AVS + kk + 8];
#pragma unroll
            for (int nf = 0; nf < 6; nf++) {
                const int c = wx * 48 + nf * 8 + g;
                uint32_t bh[2], bm_[2];
                bh[0]  = *(const uint32_t*)&Vhi[c * AVS + kk];
                bh[1]  = *(const uint32_t*)&Vhi[c * AVS + kk + 8];
                bm_[0] = *(const uint32_t*)&Vmi[c * AVS + kk];
                bm_[1] = *(const uint32_t*)&Vmi[c * AVS + kk + 8];
                mma_bf16(accO[nf], ah, bh);
                mma_bf16(accO[nf], am, bh);
                mma_bf16(accO[nf], ah, bm_);
            }
        }
    }

    // ---- normalize and write O (64 x 96) ----
    const float il0 = 1.0f / l_run0, il1 = 1.0f / l_run1;
#pragma unroll
    for (int nf = 0; nf < 6; nf++) {
        const int c = qh * HD + wx * 48 + nf * 8 + 2 * t4;
        float2 v0 = {accO[nf][0] * il0, accO[nf][1] * il0};
        float2 v1 = {accO[nf][2] * il1, accO[nf][3] * il1};
        *(float2*)(out + (size_t)(bb * SEQ + qb * 64 + r0) * EMBED + c) = v0;
        *(float2*)(out + (size_t)(bb * SEQ + qb * 64 + r1) * EMBED + c) = v1;
    }
}

// ---------------------------------------------------------------------------
// Launch
// ---------------------------------------------------------------------------
extern "C" void kernel_launch(void* const* d_in, const int* in_sizes, int n_in,
                              void* d_out, int out_size)
{
    const float* x         = (const float*)d_in[0];
    const int*   positions = (const int*)d_in[1];
    const float* W_qkv     = (const float*)d_in[3];
    const float* W_o       = (const float*)d_in[4];
    float* out = (float*)d_out;

    float* qkv;  cudaGetSymbolAddress((void**)&qkv,  g_qkv);
    float* attn; cudaGetSymbolAddress((void**)&attn, g_attn);

    cudaFuncSetAttribute(attn_mma,
                         cudaFuncAttributeMaxDynamicSharedMemorySize,
                         ATTN_SM_BYTES);

    // 1) QKV projection (bf16 tensor cores, 3-term split)
    gemm_tc<<<dim3(QKV_N / 128, ROWS / 128), 256>>>(x, W_qkv, qkv,
                                                    ROWS, QKV_N, EMBED);

    // 2) RoPE on Q and K in place
    {
        const int total = ROWS * (NQ + NKV) * (HD / 2);
        rope_kernel<<<(total + 255) / 256, 256>>>(qkv, positions);
    }

    // 3) Causal GQA attention (bf16 MMA flash)
    attn_mma<<<dim3(SEQ / 64, NQ, BATCH), 256, ATTN_SM_BYTES>>>(qkv, attn);

    // 4) Output projection (bf16 tensor cores, 3-term split)
    gemm_tc<<<dim3(EMBED / 128, ROWS / 128), 256>>>(attn, W_o, out,
                                                    ROWS, EMBED, EMBED);
}